// round 1
// baseline (speedup 1.0000x reference)
#include <cuda_runtime.h>

// CrumbReconstructor: for each 8-float block of x, find nearest of 256 codebook
// rows (squared L2) and emit that row.
//
// d_in[0] = x       fp32, [64*14*14*512] = 6,422,528  -> 802,816 blocks of 8
// d_in[1] = memory  fp32, [256, 8] = 2048
// d_out   = recon   fp32, same shape as x

#define MBLK   8
#define NCODES 256
#define KPT    4      // key-blocks per thread
#define TPB    256    // threads per CTA

__global__ __launch_bounds__(TPB)
void crumb_argmin_kernel(const float* __restrict__ x,
                         const float* __restrict__ mem,
                         float* __restrict__ out,
                         int nblocks)
{
    __shared__ float4 sA[NCODES];   // code[j][0..3]
    __shared__ float4 sB[NCODES];   // code[j][4..7]
    __shared__ float  sMM[NCODES];  // ||m_j||^2

    const int tid = threadIdx.x;

    // ---- load + preprocess codebook (one code per thread; TPB == NCODES) ----
    {
        const float4* m4 = reinterpret_cast<const float4*>(mem);
        float4 a = m4[tid * 2 + 0];
        float4 b = m4[tid * 2 + 1];
        float mm = a.x * a.x + a.y * a.y + a.z * a.z + a.w * a.w
                 + b.x * b.x + b.y * b.y + b.z * b.z + b.w * b.w;
        sA[tid] = a;
        sB[tid] = b;
        sMM[tid] = mm;
    }
    __syncthreads();

    // ---- load KPT key blocks into registers (coalesced float4) ----
    const int base = blockIdx.x * (TPB * KPT);
    const float4* x4 = reinterpret_cast<const float4*>(x);

    float4 ka[KPT], kb[KPT];
    float  kk[KPT];
    float  best[KPT];
    int    bidx[KPT];
    bool   valid[KPT];

    #pragma unroll
    for (int i = 0; i < KPT; i++) {
        int b = base + i * TPB + tid;
        valid[i] = (b < nblocks);
        int bb = valid[i] ? b : 0;
        float4 p = x4[(size_t)bb * 2 + 0];
        float4 q = x4[(size_t)bb * 2 + 1];
        ka[i] = p;
        kb[i] = q;
        kk[i] = p.x * p.x + p.y * p.y + p.z * p.z + p.w * p.w
              + q.x * q.x + q.y * q.y + q.z * q.z + q.w * q.w;
        best[i] = INFINITY;
        bidx[i] = 0;
    }

    // ---- scan all codes; ascending j + strict < == argmin first-index ----
    #pragma unroll 4
    for (int j = 0; j < NCODES; j++) {
        float4 a  = sA[j];    // warp-uniform -> LDS broadcast, conflict-free
        float4 b  = sB[j];
        float  mm = sMM[j];
        #pragma unroll
        for (int i = 0; i < KPT; i++) {
            float dot = ka[i].x * a.x;
            dot = fmaf(ka[i].y, a.y, dot);
            dot = fmaf(ka[i].z, a.z, dot);
            dot = fmaf(ka[i].w, a.w, dot);
            dot = fmaf(kb[i].x, b.x, dot);
            dot = fmaf(kb[i].y, b.y, dot);
            dot = fmaf(kb[i].z, b.z, dot);
            dot = fmaf(kb[i].w, b.w, dot);
            // d = ||k||^2 - 2 k.m + ||m||^2 ; kk is uniform in j so its
            // rounding cannot affect the argmin.
            float d = fmaf(-2.0f, dot, kk[i]) + mm;
            if (d < best[i]) { best[i] = d; bidx[i] = j; }
        }
    }

    // ---- gather winning rows from smem, coalesced float4 stores ----
    float4* o4 = reinterpret_cast<float4*>(out);
    #pragma unroll
    for (int i = 0; i < KPT; i++) {
        if (!valid[i]) continue;
        int b = base + i * TPB + tid;
        o4[(size_t)b * 2 + 0] = sA[bidx[i]];
        o4[(size_t)b * 2 + 1] = sB[bidx[i]];
    }
}

extern "C" void kernel_launch(void* const* d_in, const int* in_sizes, int n_in,
                              void* d_out, int out_size)
{
    const float* x   = (const float*)d_in[0];
    const float* mem = (const float*)d_in[1];
    float* out = (float*)d_out;

    int nblocks = in_sizes[0] / MBLK;                  // 802816
    int per_cta = TPB * KPT;                           // 1024 blocks per CTA
    int grid = (nblocks + per_cta - 1) / per_cta;      // 784

    crumb_argmin_kernel<<<grid, TPB>>>(x, mem, out, nblocks);
}

// round 3
// speedup vs baseline: 1.0423x; 1.0423x over previous
#include <cuda_runtime.h>
#include <math_constants.h>

// CrumbReconstructor: per 8-float block of x, argmin over 256 codebook rows of
// squared L2, emit the winning row.
//
// Strategy: score(j) = ||m_j||^2 - 2*k.m_j  (||k||^2 dropped: j-uniform).
// Two key-blocks packed per f32x2; codebook pre-packed in smem as dup(-2*m)
// with dup(||m||^2) as accumulator seed -> 8 FFMA2 produce both final scores.

#define MBLK   8
#define NCODES 256
#define TPB    128
#define NPAIR  4              // f32x2 pairs per thread
#define KPT    (2 * NPAIR)    // 8 key-blocks per thread

typedef unsigned long long u64;

__device__ __forceinline__ u64 pack2(float lo, float hi) {
    u64 r; asm("mov.b64 %0, {%1, %2};" : "=l"(r) : "f"(lo), "f"(hi)); return r;
}
__device__ __forceinline__ void unpack2(u64 v, float& lo, float& hi) {
    asm("mov.b64 {%0, %1}, %2;" : "=f"(lo), "=f"(hi) : "l"(v));
}
__device__ __forceinline__ u64 ffma2(u64 a, u64 b, u64 c) {
    u64 d; asm("fma.rn.f32x2 %0, %1, %2, %3;" : "=l"(d) : "l"(a), "l"(b), "l"(c));
    return d;
}

__global__ __launch_bounds__(TPB, 3)
void crumb_kernel(const float* __restrict__ x,
                  const float* __restrict__ mem,
                  float* __restrict__ out,
                  int nblocks)
{
    // [j][0..7] = dup(-2*m[j][c]), [j][8] = dup(||m_j||^2), [j][9] = pad (80B stride)
    __shared__ u64    srow[NCODES][10];
    __shared__ float4 sOrig[NCODES][2];

    const int tid = threadIdx.x;

    // ---- setup: pre-pack codebook ----
    for (int r = tid; r < NCODES; r += TPB) {
        const float4* m4 = reinterpret_cast<const float4*>(mem);
        float4 a = m4[r * 2 + 0];
        float4 b = m4[r * 2 + 1];
        float mm = a.x*a.x + a.y*a.y + a.z*a.z + a.w*a.w
                 + b.x*b.x + b.y*b.y + b.z*b.z + b.w*b.w;
        srow[r][0] = pack2(-2.f*a.x, -2.f*a.x);
        srow[r][1] = pack2(-2.f*a.y, -2.f*a.y);
        srow[r][2] = pack2(-2.f*a.z, -2.f*a.z);
        srow[r][3] = pack2(-2.f*a.w, -2.f*a.w);
        srow[r][4] = pack2(-2.f*b.x, -2.f*b.x);
        srow[r][5] = pack2(-2.f*b.y, -2.f*b.y);
        srow[r][6] = pack2(-2.f*b.z, -2.f*b.z);
        srow[r][7] = pack2(-2.f*b.w, -2.f*b.w);
        srow[r][8] = pack2(mm, mm);
        sOrig[r][0] = a;
        sOrig[r][1] = b;
    }
    __syncthreads();

    const int base = blockIdx.x * (TPB * KPT);
    const float4* x4 = reinterpret_cast<const float4*>(x);

    u64   kp[NPAIR][8];
    float bl[NPAIR], bh[NPAIR];
    int   il[NPAIR], ih[NPAIR];

    // ---- load 8 key-blocks (coalesced float4), interleave into f32x2 pairs ----
    #pragma unroll
    for (int p = 0; p < NPAIR; p++) {
        int b0 = base + (2*p + 0) * TPB + tid;
        int b1 = base + (2*p + 1) * TPB + tid;
        int c0i = (b0 < nblocks) ? b0 : 0;
        int c1i = (b1 < nblocks) ? b1 : 0;
        float4 a0 = x4[(size_t)c0i * 2 + 0], b0v = x4[(size_t)c0i * 2 + 1];
        float4 a1 = x4[(size_t)c1i * 2 + 0], b1v = x4[(size_t)c1i * 2 + 1];
        kp[p][0] = pack2(a0.x, a1.x);
        kp[p][1] = pack2(a0.y, a1.y);
        kp[p][2] = pack2(a0.z, a1.z);
        kp[p][3] = pack2(a0.w, a1.w);
        kp[p][4] = pack2(b0v.x, b1v.x);
        kp[p][5] = pack2(b0v.y, b1v.y);
        kp[p][6] = pack2(b0v.z, b1v.z);
        kp[p][7] = pack2(b0v.w, b1v.w);
        bl[p] = CUDART_INF_F; bh[p] = CUDART_INF_F;
        il[p] = 0; ih[p] = 0;
    }

    // ---- scan codes: ascending j + strict < == first-index argmin ----
    #pragma unroll 2
    for (int j = 0; j < NCODES; j++) {
        u64 c0 = srow[j][0], c1 = srow[j][1], c2 = srow[j][2], c3 = srow[j][3];
        u64 c4 = srow[j][4], c5 = srow[j][5], c6 = srow[j][6], c7 = srow[j][7];
        u64 dm = srow[j][8];
        #pragma unroll
        for (int p = 0; p < NPAIR; p++) {
            u64 d = dm;                       // seed = ||m||^2 (both halves)
            d = ffma2(kp[p][0], c0, d);
            d = ffma2(kp[p][1], c1, d);
            d = ffma2(kp[p][2], c2, d);
            d = ffma2(kp[p][3], c3, d);
            d = ffma2(kp[p][4], c4, d);
            d = ffma2(kp[p][5], c5, d);
            d = ffma2(kp[p][6], c6, d);
            d = ffma2(kp[p][7], c7, d);
            float dl, dh; unpack2(d, dl, dh);
            if (dl < bl[p]) { bl[p] = dl; il[p] = j; }
            if (dh < bh[p]) { bh[p] = dh; ih[p] = j; }
        }
    }

    // ---- gather winning rows, coalesced float4 stores ----
    float4* o4 = reinterpret_cast<float4*>(out);
    #pragma unroll
    for (int p = 0; p < NPAIR; p++) {
        int b0 = base + (2*p + 0) * TPB + tid;
        int b1 = base + (2*p + 1) * TPB + tid;
        if (b0 < nblocks) {
            o4[(size_t)b0 * 2 + 0] = sOrig[il[p]][0];
            o4[(size_t)b0 * 2 + 1] = sOrig[il[p]][1];
        }
        if (b1 < nblocks) {
            o4[(size_t)b1 * 2 + 0] = sOrig[ih[p]][0];
            o4[(size_t)b1 * 2 + 1] = sOrig[ih[p]][1];
        }
    }
}

extern "C" void kernel_launch(void* const* d_in, const int* in_sizes, int n_in,
                              void* d_out, int out_size)
{
    const float* x   = (const float*)d_in[0];
    const float* mem = (const float*)d_in[1];
    float* out = (float*)d_out;

    int nblocks = in_sizes[0] / MBLK;                 // 802816
    int per_cta = TPB * KPT;                          // 1024
    int grid = (nblocks + per_cta - 1) / per_cta;     // 784

    crumb_kernel<<<grid, TPB>>>(x, mem, out, nblocks);
}